// round 3
// baseline (speedup 1.0000x reference)
#include <cuda_runtime.h>

#define N_NODES 100000
#define F_IN 512
#define HID 16
#define CLS 7
#define HID2 8
#define E_MAX 3400000
#define NB_NODE 391          // ceil(100000/256)

// ---------------- device scratch ----------------
__device__ int   g_degi[N_NODES];
__device__ int   g_off [N_NODES + 1];
__device__ int   g_cur [N_NODES];
__device__ int   g_bsum[512];
__device__ int   g_boff[512];
__device__ float g_dinv[N_NODES];
__device__ __align__(16) float g_h1  [N_NODES * HID];
__device__ __align__(16) float g_agg1[N_NODES * HID];
__device__ __align__(16) float g_h2  [N_NODES * HID2];
__device__ __align__(16) uint2 g_csr [E_MAX];          // {src, bits(weight)}
__device__ int g_is64;

// ---------------- dtype detection for edge_index ----------------
__global__ void k_detect(const unsigned int* __restrict__ w) {
    if (threadIdx.x == 0) {
        int all0 = 1;
        #pragma unroll 1
        for (int k = 0; k < 64; k++) {
            long idx = 2L * k * 50001L + 1L;
            if (w[idx] != 0u) all0 = 0;
        }
        g_is64 = all0;
    }
}

__global__ void k_zero() {
    int i = blockIdx.x * blockDim.x + threadIdx.x;
    if (i < N_NODES) g_degi[i] = 0;
}

// ---------------- degree count (int atomics) ----------------
__global__ void k_deg(const void* __restrict__ ei, int E) {
    int i = blockIdx.x * blockDim.x + threadIdx.x;
    if (i >= E) return;
    int dst;
    if (g_is64) dst = (int)__ldg(&((const long long*)ei)[(size_t)E + i]);
    else        dst = __ldg(&((const int*)ei)[(size_t)E + i]);
    atomicAdd(&g_degi[dst], 1);
}

// ---------------- prefix scan (3 kernels) ----------------
__global__ void k_scan1() {
    __shared__ int s[256];
    int b = blockIdx.x, t = threadIdx.x;
    int i = b * 256 + t;
    int v = (i < N_NODES) ? g_degi[i] : 0;
    s[t] = v; __syncthreads();
    #pragma unroll
    for (int d = 1; d < 256; d <<= 1) {
        int add = (t >= d) ? s[t - d] : 0;
        __syncthreads();
        s[t] += add;
        __syncthreads();
    }
    if (i < N_NODES) g_off[i] = s[t] - v;   // local exclusive
    if (t == 255) g_bsum[b] = s[255];
}

__global__ void k_scan2() {
    __shared__ int s[512];
    int t = threadIdx.x;
    int v = (t < NB_NODE) ? g_bsum[t] : 0;
    s[t] = v; __syncthreads();
    #pragma unroll
    for (int d = 1; d < 512; d <<= 1) {
        int add = (t >= d) ? s[t - d] : 0;
        __syncthreads();
        s[t] += add;
        __syncthreads();
    }
    if (t < NB_NODE) g_boff[t] = s[t] - v;  // exclusive block offset
}

__global__ void k_scan3(int E) {
    int i = blockIdx.x * blockDim.x + threadIdx.x;
    if (i >= N_NODES) return;
    int off = g_off[i] + g_boff[i >> 8];
    g_off[i] = off;
    g_cur[i] = off;
    g_dinv[i] = rsqrtf((float)(g_degi[i] + 1));  // +1 self loop
    if (i == N_NODES - 1) g_off[N_NODES] = E;
}

// ---------------- CSR build: scatter {src, weight} by dst ----------------
__global__ void k_build(const void* __restrict__ ei, int E) {
    int i = blockIdx.x * blockDim.x + threadIdx.x;
    if (i >= E) return;
    int src, dst;
    if (g_is64) {
        const long long* e = (const long long*)ei;
        src = (int)__ldg(&e[i]); dst = (int)__ldg(&e[(size_t)E + i]);
    } else {
        const int* e = (const int*)ei;
        src = __ldg(&e[i]); dst = __ldg(&e[(size_t)E + i]);
    }
    float w = __ldg(&g_dinv[src]) * __ldg(&g_dinv[dst]);
    int pos = atomicAdd(&g_cur[dst], 1);
    g_csr[pos] = make_uint2((unsigned)src, __float_as_uint(w));
}

// ---------------- GEMM1: h1 = x @ W1 (2 rows per thread) ----------------
#define G1_TPB 128
__global__ void k_gemm1(const float* __restrict__ x, const float* __restrict__ W1) {
    __shared__ float Ws[F_IN * HID];                       // 32 KB
    {
        float4* wd = (float4*)Ws;
        const float4* wsrc = (const float4*)W1;
        for (int i = threadIdx.x; i < F_IN * HID / 4; i += G1_TPB) wd[i] = __ldg(&wsrc[i]);
    }
    __syncthreads();

    int base = blockIdx.x * (G1_TPB * 2) + threadIdx.x;
    int r0 = base < N_NODES ? base : N_NODES - 1;
    int r1 = (base + G1_TPB) < N_NODES ? (base + G1_TPB) : N_NODES - 1;

    float acc0[HID], acc1[HID];
    #pragma unroll
    for (int j = 0; j < HID; j++) { acc0[j] = 0.0f; acc1[j] = 0.0f; }

    const float4* x0 = (const float4*)(x + (size_t)r0 * F_IN);
    const float4* x1 = (const float4*)(x + (size_t)r1 * F_IN);

    #pragma unroll 4
    for (int kq = 0; kq < F_IN / 4; kq++) {
        float4 xv0 = __ldg(&x0[kq]);
        float4 xv1 = __ldg(&x1[kq]);
        #pragma unroll
        for (int kk = 0; kk < 4; kk++) {
            const float4* wr = (const float4*)&Ws[(kq * 4 + kk) * HID];
            float4 w0 = wr[0], w1 = wr[1], w2 = wr[2], w3 = wr[3];
            float a0 = ((const float*)&xv0)[kk];
            float a1 = ((const float*)&xv1)[kk];
            acc0[0]  = fmaf(a0, w0.x, acc0[0]);  acc1[0]  = fmaf(a1, w0.x, acc1[0]);
            acc0[1]  = fmaf(a0, w0.y, acc0[1]);  acc1[1]  = fmaf(a1, w0.y, acc1[1]);
            acc0[2]  = fmaf(a0, w0.z, acc0[2]);  acc1[2]  = fmaf(a1, w0.z, acc1[2]);
            acc0[3]  = fmaf(a0, w0.w, acc0[3]);  acc1[3]  = fmaf(a1, w0.w, acc1[3]);
            acc0[4]  = fmaf(a0, w1.x, acc0[4]);  acc1[4]  = fmaf(a1, w1.x, acc1[4]);
            acc0[5]  = fmaf(a0, w1.y, acc0[5]);  acc1[5]  = fmaf(a1, w1.y, acc1[5]);
            acc0[6]  = fmaf(a0, w1.z, acc0[6]);  acc1[6]  = fmaf(a1, w1.z, acc1[6]);
            acc0[7]  = fmaf(a0, w1.w, acc0[7]);  acc1[7]  = fmaf(a1, w1.w, acc1[7]);
            acc0[8]  = fmaf(a0, w2.x, acc0[8]);  acc1[8]  = fmaf(a1, w2.x, acc1[8]);
            acc0[9]  = fmaf(a0, w2.y, acc0[9]);  acc1[9]  = fmaf(a1, w2.y, acc1[9]);
            acc0[10] = fmaf(a0, w2.z, acc0[10]); acc1[10] = fmaf(a1, w2.z, acc1[10]);
            acc0[11] = fmaf(a0, w2.w, acc0[11]); acc1[11] = fmaf(a1, w2.w, acc1[11]);
            acc0[12] = fmaf(a0, w3.x, acc0[12]); acc1[12] = fmaf(a1, w3.x, acc1[12]);
            acc0[13] = fmaf(a0, w3.y, acc0[13]); acc1[13] = fmaf(a1, w3.y, acc1[13]);
            acc0[14] = fmaf(a0, w3.z, acc0[14]); acc1[14] = fmaf(a1, w3.z, acc1[14]);
            acc0[15] = fmaf(a0, w3.w, acc0[15]); acc1[15] = fmaf(a1, w3.w, acc1[15]);
        }
    }
    if (base < N_NODES) {
        float4* o = (float4*)(g_h1 + (size_t)base * HID);
        o[0] = make_float4(acc0[0], acc0[1], acc0[2], acc0[3]);
        o[1] = make_float4(acc0[4], acc0[5], acc0[6], acc0[7]);
        o[2] = make_float4(acc0[8], acc0[9], acc0[10], acc0[11]);
        o[3] = make_float4(acc0[12], acc0[13], acc0[14], acc0[15]);
    }
    if (base + G1_TPB < N_NODES) {
        float4* o = (float4*)(g_h1 + (size_t)(base + G1_TPB) * HID);
        o[0] = make_float4(acc1[0], acc1[1], acc1[2], acc1[3]);
        o[1] = make_float4(acc1[4], acc1[5], acc1[6], acc1[7]);
        o[2] = make_float4(acc1[8], acc1[9], acc1[10], acc1[11]);
        o[3] = make_float4(acc1[12], acc1[13], acc1[14], acc1[15]);
    }
}

// ---------------- gather layer 1: warp per node, no atomics ----------------
__global__ void k_gather1() {
    int warp = (blockIdx.x * blockDim.x + threadIdx.x) >> 5;
    if (warp >= N_NODES) return;
    int lane = threadIdx.x & 31;
    int eslot = lane >> 2;          // 0..7
    int q     = lane & 3;           // float4 chunk 0..3

    int beg = __ldg(&g_off[warp]);
    int end = __ldg(&g_off[warp + 1]);

    float4 acc = make_float4(0.f, 0.f, 0.f, 0.f);
    for (int e = beg + eslot; e < end; e += 8) {
        uint2 ent = __ldg(&g_csr[e]);
        float w = __uint_as_float(ent.y);
        float4 v = __ldg((const float4*)(g_h1 + (size_t)ent.x * HID) + q);
        acc.x = fmaf(v.x, w, acc.x);
        acc.y = fmaf(v.y, w, acc.y);
        acc.z = fmaf(v.z, w, acc.z);
        acc.w = fmaf(v.w, w, acc.w);
    }
    #pragma unroll
    for (int m = 4; m <= 16; m <<= 1) {
        acc.x += __shfl_xor_sync(0xffffffffu, acc.x, m);
        acc.y += __shfl_xor_sync(0xffffffffu, acc.y, m);
        acc.z += __shfl_xor_sync(0xffffffffu, acc.z, m);
        acc.w += __shfl_xor_sync(0xffffffffu, acc.w, m);
    }
    if (lane < 4)
        *((float4*)(g_agg1 + (size_t)warp * HID) + q) = acc;
}

// ---------------- mid: self loop + bias + relu + GEMM2 -> h2 ----------------
__global__ void k_mid(const float* __restrict__ b1, const float* __restrict__ W2) {
    __shared__ float Ws[HID * CLS];
    if (threadIdx.x < HID * CLS) Ws[threadIdx.x] = W2[threadIdx.x];
    __syncthreads();

    int i = blockIdx.x * blockDim.x + threadIdx.x;
    if (i >= N_NODES) return;
    float dv = g_dinv[i];
    float d2 = dv * dv;

    float r[HID];
    const float4* a = (const float4*)(g_agg1 + (size_t)i * HID);
    const float4* h = (const float4*)(g_h1   + (size_t)i * HID);
    const float4* bb = (const float4*)b1;
    #pragma unroll
    for (int qn = 0; qn < 4; qn++) {
        float4 av = a[qn], hv = h[qn], bv = __ldg(&bb[qn]);
        r[qn * 4 + 0] = fmaxf(av.x + d2 * hv.x + bv.x, 0.0f);
        r[qn * 4 + 1] = fmaxf(av.y + d2 * hv.y + bv.y, 0.0f);
        r[qn * 4 + 2] = fmaxf(av.z + d2 * hv.z + bv.z, 0.0f);
        r[qn * 4 + 3] = fmaxf(av.w + d2 * hv.w + bv.w, 0.0f);
    }
    float acc[CLS];
    #pragma unroll
    for (int j = 0; j < CLS; j++) acc[j] = 0.0f;
    #pragma unroll
    for (int k = 0; k < HID; k++) {
        float rv = r[k];
        #pragma unroll
        for (int j = 0; j < CLS; j++) acc[j] = fmaf(rv, Ws[k * CLS + j], acc[j]);
    }
    float4* o = (float4*)(g_h2 + (size_t)i * HID2);
    o[0] = make_float4(acc[0], acc[1], acc[2], acc[3]);
    o[1] = make_float4(acc[4], acc[5], acc[6], 0.0f);
}

// ---------------- gather layer 2 + finalize -> out ----------------
__global__ void k_gather2(const float* __restrict__ b2, float* __restrict__ out) {
    int warp = (blockIdx.x * blockDim.x + threadIdx.x) >> 5;
    if (warp >= N_NODES) return;
    int lane = threadIdx.x & 31;
    int eslot = lane >> 1;          // 0..15
    int half  = lane & 1;           // which float4 of h2

    int beg = __ldg(&g_off[warp]);
    int end = __ldg(&g_off[warp + 1]);

    float4 acc = make_float4(0.f, 0.f, 0.f, 0.f);
    for (int e = beg + eslot; e < end; e += 16) {
        uint2 ent = __ldg(&g_csr[e]);
        float w = __uint_as_float(ent.y);
        float4 v = __ldg((const float4*)(g_h2 + (size_t)ent.x * HID2) + half);
        acc.x = fmaf(v.x, w, acc.x);
        acc.y = fmaf(v.y, w, acc.y);
        acc.z = fmaf(v.z, w, acc.z);
        acc.w = fmaf(v.w, w, acc.w);
    }
    #pragma unroll
    for (int m = 2; m <= 16; m <<= 1) {
        acc.x += __shfl_xor_sync(0xffffffffu, acc.x, m);
        acc.y += __shfl_xor_sync(0xffffffffu, acc.y, m);
        acc.z += __shfl_xor_sync(0xffffffffu, acc.z, m);
        acc.w += __shfl_xor_sync(0xffffffffu, acc.w, m);
    }
    if (lane < 2) {
        float dv = g_dinv[warp];
        float d2 = dv * dv;
        float4 hv = *((const float4*)(g_h2 + (size_t)warp * HID2) + half);
        float o0 = acc.x + d2 * hv.x;
        float o1 = acc.y + d2 * hv.y;
        float o2 = acc.z + d2 * hv.z;
        float o3 = acc.w + d2 * hv.w;
        float* op = out + (size_t)warp * CLS + half * 4;
        if (half == 0) {
            op[0] = o0 + __ldg(&b2[0]);
            op[1] = o1 + __ldg(&b2[1]);
            op[2] = o2 + __ldg(&b2[2]);
            op[3] = o3 + __ldg(&b2[3]);
        } else {
            op[0] = o0 + __ldg(&b2[4]);
            op[1] = o1 + __ldg(&b2[5]);
            op[2] = o2 + __ldg(&b2[6]);
        }
    }
}

// ---------------- launch ----------------
extern "C" void kernel_launch(void* const* d_in, const int* in_sizes, int n_in,
                              void* d_out, int out_size) {
    const float* x  = (const float*)d_in[0];
    const void*  ei = d_in[1];
    const float* W1 = (const float*)d_in[2];
    const float* b1 = (const float*)d_in[3];
    const float* W2 = (const float*)d_in[4];
    const float* b2 = (const float*)d_in[5];
    float* out = (float*)d_out;

    int E = in_sizes[1] / 2;

    const int TPB = 256;
    int nbE = (E + TPB - 1) / TPB;
    int nbG = (N_NODES * 32 + TPB - 1) / TPB;   // warp per node
    int nbG1m = (N_NODES + G1_TPB * 2 - 1) / (G1_TPB * 2);

    k_detect<<<1, 32>>>((const unsigned int*)ei);
    k_zero  <<<NB_NODE, TPB>>>();
    k_deg   <<<nbE, TPB>>>(ei, E);
    k_scan1 <<<NB_NODE, TPB>>>();
    k_scan2 <<<1, 512>>>();
    k_scan3 <<<NB_NODE, TPB>>>(E);
    k_build <<<nbE, TPB>>>(ei, E);
    k_gemm1 <<<nbG1m, G1_TPB>>>(x, W1);
    k_gather1<<<nbG, TPB>>>();
    k_mid   <<<NB_NODE, TPB>>>(b1, W2);
    k_gather2<<<nbG, TPB>>>(b2, out);
}

// round 7
// speedup vs baseline: 1.3293x; 1.3293x over previous
#include <cuda_runtime.h>

#define N_NODES 100000
#define F_IN 512
#define HID 16
#define CLS 7
#define HID2 8
#define E_MAX 3400000
#define NB_NODE 391          // ceil(100000/256)

// ---------------- device scratch ----------------
__device__ int   g_degi[N_NODES];
__device__ int   g_off [N_NODES + 1];
__device__ int   g_cur [N_NODES];
__device__ int   g_bsum[512];
__device__ int   g_boff[512];
__device__ float g_dinv[N_NODES];
__device__ __align__(16) float g_h1  [N_NODES * HID];
__device__ __align__(16) float g_agg1[N_NODES * HID];
__device__ __align__(16) float g_h2  [N_NODES * HID2];
__device__ __align__(16) uint2 g_csr [E_MAX];          // {src, bits(weight)}
__device__ int g_is64;

// ---------------- dtype detection for edge_index ----------------
__global__ void k_detect(const unsigned int* __restrict__ w) {
    if (threadIdx.x == 0) {
        int all0 = 1;
        #pragma unroll 1
        for (int k = 0; k < 64; k++) {
            long idx = 2L * k * 50001L + 1L;
            if (w[idx] != 0u) all0 = 0;
        }
        g_is64 = all0;
    }
}

__global__ void k_zero() {
    int i = blockIdx.x * blockDim.x + threadIdx.x;
    if (i < N_NODES) g_degi[i] = 0;
}

// ---------------- degree count (int atomics) ----------------
__global__ void k_deg(const void* __restrict__ ei, int E) {
    int i = blockIdx.x * blockDim.x + threadIdx.x;
    if (i >= E) return;
    int dst;
    if (g_is64) dst = (int)__ldg(&((const long long*)ei)[(size_t)E + i]);
    else        dst = __ldg(&((const int*)ei)[(size_t)E + i]);
    atomicAdd(&g_degi[dst], 1);
}

// ---------------- GEMM1: h1 = x @ W1, smem-staged coalesced ----------------
// Block: 128 threads = 128 rows. K chunked by 32.
// x tile loaded coalesced into padded smem (stride 36 words), W chunk in smem.
#define G1_TPB   128
#define KC       32
#define XS_STRIDE 36           // 32 + pad, multiple of 4 for float4 stores
__global__ void k_gemm1(const float* __restrict__ x, const float* __restrict__ W1) {
    __shared__ float xs[G1_TPB * XS_STRIDE];   // 18 KB
    __shared__ float ws[KC * HID];             // 2 KB

    int t = threadIdx.x;
    int rowbase = blockIdx.x * G1_TPB;

    float acc[HID];
    #pragma unroll
    for (int j = 0; j < HID; j++) acc[j] = 0.0f;

    for (int ch = 0; ch < F_IN / KC; ch++) {
        // load W chunk: KC*HID = 512 floats = 128 float4, 1 per thread
        {
            const float4* wsrc = (const float4*)(W1 + ch * KC * HID);
            ((float4*)ws)[t] = __ldg(&wsrc[t]);
        }
        // load x tile coalesced: 128 rows x 32 cols = 1024 float4, 8 per thread
        #pragma unroll
        for (int i = 0; i < 8; i++) {
            int f   = t + i * G1_TPB;          // float4 index in tile
            int row = f >> 3;                  // 8 float4 per row
            int c4  = f & 7;
            int grow = rowbase + row;
            if (grow >= N_NODES) grow = N_NODES - 1;
            float4 v = __ldg((const float4*)(x + (size_t)grow * F_IN + ch * KC) + c4);
            *(float4*)&xs[row * XS_STRIDE + c4 * 4] = v;
        }
        __syncthreads();

        // compute: this thread's row from smem
        #pragma unroll
        for (int k4 = 0; k4 < KC / 4; k4++) {
            float4 xv = *(const float4*)&xs[t * XS_STRIDE + k4 * 4];
            #pragma unroll
            for (int kk = 0; kk < 4; kk++) {
                const float4* wr = (const float4*)&ws[(k4 * 4 + kk) * HID];
                float4 w0 = wr[0], w1 = wr[1], w2 = wr[2], w3 = wr[3];
                float a = ((const float*)&xv)[kk];
                acc[0]  = fmaf(a, w0.x, acc[0]);
                acc[1]  = fmaf(a, w0.y, acc[1]);
                acc[2]  = fmaf(a, w0.z, acc[2]);
                acc[3]  = fmaf(a, w0.w, acc[3]);
                acc[4]  = fmaf(a, w1.x, acc[4]);
                acc[5]  = fmaf(a, w1.y, acc[5]);
                acc[6]  = fmaf(a, w1.z, acc[6]);
                acc[7]  = fmaf(a, w1.w, acc[7]);
                acc[8]  = fmaf(a, w2.x, acc[8]);
                acc[9]  = fmaf(a, w2.y, acc[9]);
                acc[10] = fmaf(a, w2.z, acc[10]);
                acc[11] = fmaf(a, w2.w, acc[11]);
                acc[12] = fmaf(a, w3.x, acc[12]);
                acc[13] = fmaf(a, w3.y, acc[13]);
                acc[14] = fmaf(a, w3.z, acc[14]);
                acc[15] = fmaf(a, w3.w, acc[15]);
            }
        }
        __syncthreads();
    }

    int row = rowbase + t;
    if (row < N_NODES) {
        float4* o = (float4*)(g_h1 + (size_t)row * HID);
        o[0] = make_float4(acc[0],  acc[1],  acc[2],  acc[3]);
        o[1] = make_float4(acc[4],  acc[5],  acc[6],  acc[7]);
        o[2] = make_float4(acc[8],  acc[9],  acc[10], acc[11]);
        o[3] = make_float4(acc[12], acc[13], acc[14], acc[15]);
    }
}

// ---------------- prefix scan (3 kernels) ----------------
__global__ void k_scan1() {
    __shared__ int s[256];
    int b = blockIdx.x, t = threadIdx.x;
    int i = b * 256 + t;
    int v = (i < N_NODES) ? g_degi[i] : 0;
    s[t] = v; __syncthreads();
    #pragma unroll
    for (int d = 1; d < 256; d <<= 1) {
        int add = (t >= d) ? s[t - d] : 0;
        __syncthreads();
        s[t] += add;
        __syncthreads();
    }
    if (i < N_NODES) g_off[i] = s[t] - v;   // local exclusive
    if (t == 255) g_bsum[b] = s[255];
}

__global__ void k_scan2() {
    __shared__ int s[512];
    int t = threadIdx.x;
    int v = (t < NB_NODE) ? g_bsum[t] : 0;
    s[t] = v; __syncthreads();
    #pragma unroll
    for (int d = 1; d < 512; d <<= 1) {
        int add = (t >= d) ? s[t - d] : 0;
        __syncthreads();
        s[t] += add;
        __syncthreads();
    }
    if (t < NB_NODE) g_boff[t] = s[t] - v;  // exclusive block offset
}

__global__ void k_scan3(int E) {
    int i = blockIdx.x * blockDim.x + threadIdx.x;
    if (i >= N_NODES) return;
    int off = g_off[i] + g_boff[i >> 8];
    g_off[i] = off;
    g_cur[i] = off;
    g_dinv[i] = rsqrtf((float)(g_degi[i] + 1));  // +1 self loop
    if (i == N_NODES - 1) g_off[N_NODES] = E;
}

// ---------------- CSR build: scatter {src, weight} by dst ----------------
__global__ void k_build(const void* __restrict__ ei, int E) {
    int i = blockIdx.x * blockDim.x + threadIdx.x;
    if (i >= E) return;
    int src, dst;
    if (g_is64) {
        const long long* e = (const long long*)ei;
        src = (int)__ldg(&e[i]); dst = (int)__ldg(&e[(size_t)E + i]);
    } else {
        const int* e = (const int*)ei;
        src = __ldg(&e[i]); dst = __ldg(&e[(size_t)E + i]);
    }
    float w = __ldg(&g_dinv[src]) * __ldg(&g_dinv[dst]);
    int pos = atomicAdd(&g_cur[dst], 1);
    g_csr[pos] = make_uint2((unsigned)src, __float_as_uint(w));
}

// ---------------- gather layer 1: warp per node, no atomics ----------------
__global__ void k_gather1() {
    int warp = (blockIdx.x * blockDim.x + threadIdx.x) >> 5;
    if (warp >= N_NODES) return;
    int lane = threadIdx.x & 31;
    int eslot = lane >> 2;          // 0..7
    int q     = lane & 3;           // float4 chunk 0..3

    int beg = __ldg(&g_off[warp]);
    int end = __ldg(&g_off[warp + 1]);

    float4 acc = make_float4(0.f, 0.f, 0.f, 0.f);
    for (int e = beg + eslot; e < end; e += 8) {
        uint2 ent = __ldg(&g_csr[e]);
        float w = __uint_as_float(ent.y);
        float4 v = __ldg((const float4*)(g_h1 + (size_t)ent.x * HID) + q);
        acc.x = fmaf(v.x, w, acc.x);
        acc.y = fmaf(v.y, w, acc.y);
        acc.z = fmaf(v.z, w, acc.z);
        acc.w = fmaf(v.w, w, acc.w);
    }
    #pragma unroll
    for (int m = 4; m <= 16; m <<= 1) {
        acc.x += __shfl_xor_sync(0xffffffffu, acc.x, m);
        acc.y += __shfl_xor_sync(0xffffffffu, acc.y, m);
        acc.z += __shfl_xor_sync(0xffffffffu, acc.z, m);
        acc.w += __shfl_xor_sync(0xffffffffu, acc.w, m);
    }
    if (lane < 4)
        *((float4*)(g_agg1 + (size_t)warp * HID) + q) = acc;
}

// ---------------- mid: self loop + bias + relu + GEMM2 -> h2 ----------------
__global__ void k_mid(const float* __restrict__ b1, const float* __restrict__ W2) {
    __shared__ float Ws[HID * CLS];
    if (threadIdx.x < HID * CLS) Ws[threadIdx.x] = W2[threadIdx.x];
    __syncthreads();

    int i = blockIdx.x * blockDim.x + threadIdx.x;
    if (i >= N_NODES) return;
    float dv = g_dinv[i];
    float d2 = dv * dv;

    float r[HID];
    const float4* a = (const float4*)(g_agg1 + (size_t)i * HID);
    const float4* h = (const float4*)(g_h1   + (size_t)i * HID);
    const float4* bb = (const float4*)b1;
    #pragma unroll
    for (int qn = 0; qn < 4; qn++) {
        float4 av = a[qn], hv = h[qn], bv = __ldg(&bb[qn]);
        r[qn * 4 + 0] = fmaxf(av.x + d2 * hv.x + bv.x, 0.0f);
        r[qn * 4 + 1] = fmaxf(av.y + d2 * hv.y + bv.y, 0.0f);
        r[qn * 4 + 2] = fmaxf(av.z + d2 * hv.z + bv.z, 0.0f);
        r[qn * 4 + 3] = fmaxf(av.w + d2 * hv.w + bv.w, 0.0f);
    }
    float acc[CLS];
    #pragma unroll
    for (int j = 0; j < CLS; j++) acc[j] = 0.0f;
    #pragma unroll
    for (int k = 0; k < HID; k++) {
        float rv = r[k];
        #pragma unroll
        for (int j = 0; j < CLS; j++) acc[j] = fmaf(rv, Ws[k * CLS + j], acc[j]);
    }
    float4* o = (float4*)(g_h2 + (size_t)i * HID2);
    o[0] = make_float4(acc[0], acc[1], acc[2], acc[3]);
    o[1] = make_float4(acc[4], acc[5], acc[6], 0.0f);
}

// ---------------- gather layer 2 + finalize -> out ----------------
__global__ void k_gather2(const float* __restrict__ b2, float* __restrict__ out) {
    int warp = (blockIdx.x * blockDim.x + threadIdx.x) >> 5;
    if (warp >= N_NODES) return;
    int lane = threadIdx.x & 31;
    int eslot = lane >> 1;          // 0..15
    int half  = lane & 1;           // which float4 of h2

    int beg = __ldg(&g_off[warp]);
    int end = __ldg(&g_off[warp + 1]);

    float4 acc = make_float4(0.f, 0.f, 0.f, 0.f);
    for (int e = beg + eslot; e < end; e += 16) {
        uint2 ent = __ldg(&g_csr[e]);
        float w = __uint_as_float(ent.y);
        float4 v = __ldg((const float4*)(g_h2 + (size_t)ent.x * HID2) + half);
        acc.x = fmaf(v.x, w, acc.x);
        acc.y = fmaf(v.y, w, acc.y);
        acc.z = fmaf(v.z, w, acc.z);
        acc.w = fmaf(v.w, w, acc.w);
    }
    #pragma unroll
    for (int m = 2; m <= 16; m <<= 1) {
        acc.x += __shfl_xor_sync(0xffffffffu, acc.x, m);
        acc.y += __shfl_xor_sync(0xffffffffu, acc.y, m);
        acc.z += __shfl_xor_sync(0xffffffffu, acc.z, m);
        acc.w += __shfl_xor_sync(0xffffffffu, acc.w, m);
    }
    if (lane < 2) {
        float dv = g_dinv[warp];
        float d2 = dv * dv;
        float4 hv = *((const float4*)(g_h2 + (size_t)warp * HID2) + half);
        float o0 = acc.x + d2 * hv.x;
        float o1 = acc.y + d2 * hv.y;
        float o2 = acc.z + d2 * hv.z;
        float o3 = acc.w + d2 * hv.w;
        float* op = out + (size_t)warp * CLS + half * 4;
        if (half == 0) {
            op[0] = o0 + __ldg(&b2[0]);
            op[1] = o1 + __ldg(&b2[1]);
            op[2] = o2 + __ldg(&b2[2]);
            op[3] = o3 + __ldg(&b2[3]);
        } else {
            op[0] = o0 + __ldg(&b2[4]);
            op[1] = o1 + __ldg(&b2[5]);
            op[2] = o2 + __ldg(&b2[6]);
        }
    }
}

// ---------------- launch ----------------
extern "C" void kernel_launch(void* const* d_in, const int* in_sizes, int n_in,
                              void* d_out, int out_size) {
    const float* x  = (const float*)d_in[0];
    const void*  ei = d_in[1];
    const float* W1 = (const float*)d_in[2];
    const float* b1 = (const float*)d_in[3];
    const float* W2 = (const float*)d_in[4];
    const float* b2 = (const float*)d_in[5];
    float* out = (float*)d_out;

    int E = in_sizes[1] / 2;

    const int TPB = 256;
    int nbE = (E + TPB - 1) / TPB;
    int nbG = (N_NODES * 32 + TPB - 1) / TPB;   // warp per node
    int nbG1 = (N_NODES + G1_TPB - 1) / G1_TPB;

    // gemm1 placed 4th: ncu capture lands on the 4th launch
    k_detect<<<1, 32>>>((const unsigned int*)ei);
    k_zero  <<<NB_NODE, TPB>>>();
    k_deg   <<<nbE, TPB>>>(ei, E);
    k_gemm1 <<<nbG1, G1_TPB>>>(x, W1);
    k_scan1 <<<NB_NODE, TPB>>>();
    k_scan2 <<<1, 512>>>();
    k_scan3 <<<NB_NODE, TPB>>>(E);
    k_build <<<nbE, TPB>>>(ei, E);
    k_gather1<<<nbG, TPB>>>();
    k_mid   <<<NB_NODE, TPB>>>(b1, W2);
    k_gather2<<<nbG, TPB>>>(b2, out);
}

// round 9
// speedup vs baseline: 1.4282x; 1.0744x over previous
#include <cuda_runtime.h>

#define N_NODES 100000
#define F_IN 512
#define HID 16
#define CLS 7
#define HID2 8
#define E_MAX 3400000
#define NB_NODE 391          // ceil(100000/256)

// ---------------- device scratch ----------------
__device__ int   g_degi[N_NODES];
__device__ int   g_off [N_NODES + 1];
__device__ int   g_cur [N_NODES];
__device__ int   g_bsum[512];
__device__ float g_dinv[N_NODES];
__device__ __align__(16) float g_h1 [N_NODES * HID];
__device__ __align__(16) float g_h2 [N_NODES * HID2];
__device__ __align__(16) uint2 g_csr[E_MAX];           // {src, bits(weight)}
__device__ int g_is64;

// ---------------- detect dtype + zero degrees (fused) ----------------
__global__ void k_detect_zero(const unsigned int* __restrict__ w) {
    int i = blockIdx.x * blockDim.x + threadIdx.x;
    if (i < N_NODES) g_degi[i] = 0;
    if (i == 0) {
        int all0 = 1;
        #pragma unroll 1
        for (int k = 0; k < 64; k++) {
            long idx = 2L * k * 50001L + 1L;
            if (w[idx] != 0u) all0 = 0;
        }
        g_is64 = all0;
    }
}

// ---------------- degree count (int atomics) ----------------
__global__ void k_deg(const void* __restrict__ ei, int E) {
    int i = blockIdx.x * blockDim.x + threadIdx.x;
    if (i >= E) return;
    int dst;
    if (g_is64) dst = (int)__ldg(&((const long long*)ei)[(size_t)E + i]);
    else        dst = __ldg(&((const int*)ei)[(size_t)E + i]);
    atomicAdd(&g_degi[dst], 1);
}

// ---------------- scan stage 1: per-block exclusive scan ----------------
__global__ void k_scan1() {
    __shared__ int s[256];
    int b = blockIdx.x, t = threadIdx.x;
    int i = b * 256 + t;
    int v = (i < N_NODES) ? g_degi[i] : 0;
    s[t] = v; __syncthreads();
    #pragma unroll
    for (int d = 1; d < 256; d <<= 1) {
        int add = (t >= d) ? s[t - d] : 0;
        __syncthreads();
        s[t] += add;
        __syncthreads();
    }
    if (i < N_NODES) g_off[i] = s[t] - v;   // local exclusive
    if (t == 255) g_bsum[b] = s[255];
}

// ---------------- scan stage 2 (block offsets computed per-block) + dinv ----
__global__ void k_scan3(int E) {
    __shared__ int sb[256];
    int t = threadIdx.x, b = blockIdx.x;
    int part = 0;
    for (int j = t; j < b; j += 256) part += g_bsum[j];
    sb[t] = part; __syncthreads();
    #pragma unroll
    for (int d = 128; d > 0; d >>= 1) {
        if (t < d) sb[t] += sb[t + d];
        __syncthreads();
    }
    int boff = sb[0];
    int i = b * 256 + t;
    if (i < N_NODES) {
        int off = g_off[i] + boff;
        g_off[i] = off;
        g_cur[i] = off;
        g_dinv[i] = rsqrtf((float)(g_degi[i] + 1));  // +1 self loop
        if (i == N_NODES - 1) g_off[N_NODES] = E;
    }
}

// ---------------- CSR build: scatter {src, weight} by dst ----------------
__global__ void k_build(const void* __restrict__ ei, int E) {
    int i = blockIdx.x * blockDim.x + threadIdx.x;
    if (i >= E) return;
    int src, dst;
    if (g_is64) {
        const long long* e = (const long long*)ei;
        src = (int)__ldg(&e[i]); dst = (int)__ldg(&e[(size_t)E + i]);
    } else {
        const int* e = (const int*)ei;
        src = __ldg(&e[i]); dst = __ldg(&e[(size_t)E + i]);
    }
    float w = __ldg(&g_dinv[src]) * __ldg(&g_dinv[dst]);
    int pos = atomicAdd(&g_cur[dst], 1);
    g_csr[pos] = make_uint2((unsigned)src, __float_as_uint(w));
}

// ---------------- GEMM1: h1 = x @ W1, 4 rows/thread, KC=16 ----------------
#define G1_TPB  128
#define G1_ROWS 512            // rows per block = 4 * G1_TPB
#define KC      16
#define XS2     20             // 16 + pad, multiple of 4
__global__ void __launch_bounds__(G1_TPB)
k_gemm1(const float* __restrict__ x, const float* __restrict__ W1) {
    __shared__ float xs[G1_ROWS * XS2];        // 40 KB
    __shared__ float ws[KC * HID];             // 1 KB

    int t = threadIdx.x;
    int rowbase = blockIdx.x * G1_ROWS;

    float acc[4][HID];
    #pragma unroll
    for (int r = 0; r < 4; r++)
        #pragma unroll
        for (int j = 0; j < HID; j++) acc[r][j] = 0.0f;

    #pragma unroll 1
    for (int ch = 0; ch < F_IN / KC; ch++) {
        // W chunk: KC*HID = 256 floats = 64 float4
        if (t < 64) {
            const float4* wsrc = (const float4*)(W1 + ch * KC * HID);
            ((float4*)ws)[t] = __ldg(&wsrc[t]);
        }
        // x tile coalesced: 512 rows x 16 cols = 2048 float4, 16 per thread
        #pragma unroll
        for (int i = 0; i < 16; i++) {
            int f   = t + i * G1_TPB;
            int row = f >> 2;                  // 4 float4 per row
            int c4  = f & 3;
            int grow = rowbase + row;
            if (grow >= N_NODES) grow = N_NODES - 1;
            float4 v = __ldg((const float4*)(x + (size_t)grow * F_IN + ch * KC) + c4);
            *(float4*)&xs[row * XS2 + c4 * 4] = v;
        }
        __syncthreads();

        #pragma unroll
        for (int k4 = 0; k4 < KC / 4; k4++) {
            float4 xv0 = *(const float4*)&xs[(t          ) * XS2 + k4 * 4];
            float4 xv1 = *(const float4*)&xs[(t + G1_TPB ) * XS2 + k4 * 4];
            float4 xv2 = *(const float4*)&xs[(t + 2*G1_TPB) * XS2 + k4 * 4];
            float4 xv3 = *(const float4*)&xs[(t + 3*G1_TPB) * XS2 + k4 * 4];
            #pragma unroll
            for (int kk = 0; kk < 4; kk++) {
                const float4* wr = (const float4*)&ws[(k4 * 4 + kk) * HID];
                float4 w0 = wr[0], w1 = wr[1], w2 = wr[2], w3 = wr[3];
                float a0 = ((const float*)&xv0)[kk];
                float a1 = ((const float*)&xv1)[kk];
                float a2 = ((const float*)&xv2)[kk];
                float a3 = ((const float*)&xv3)[kk];
                const float wv[16] = {w0.x,w0.y,w0.z,w0.w, w1.x,w1.y,w1.z,w1.w,
                                      w2.x,w2.y,w2.z,w2.w, w3.x,w3.y,w3.z,w3.w};
                #pragma unroll
                for (int j = 0; j < HID; j++) {
                    acc[0][j] = fmaf(a0, wv[j], acc[0][j]);
                    acc[1][j] = fmaf(a1, wv[j], acc[1][j]);
                    acc[2][j] = fmaf(a2, wv[j], acc[2][j]);
                    acc[3][j] = fmaf(a3, wv[j], acc[3][j]);
                }
            }
        }
        __syncthreads();
    }

    #pragma unroll
    for (int r = 0; r < 4; r++) {
        int row = rowbase + t + r * G1_TPB;
        if (row < N_NODES) {
            float4* o = (float4*)(g_h1 + (size_t)row * HID);
            o[0] = make_float4(acc[r][0],  acc[r][1],  acc[r][2],  acc[r][3]);
            o[1] = make_float4(acc[r][4],  acc[r][5],  acc[r][6],  acc[r][7]);
            o[2] = make_float4(acc[r][8],  acc[r][9],  acc[r][10], acc[r][11]);
            o[3] = make_float4(acc[r][12], acc[r][13], acc[r][14], acc[r][15]);
        }
    }
}

// ------- gather layer 1 + selfloop + bias + relu + GEMM2 -> h2 (fused) -----
#define GTPB 256
__global__ void k_gather1(const float* __restrict__ b1, const float* __restrict__ W2) {
    __shared__ float Ws2[HID * HID2];   // W2 padded to 8 cols (col 7 = 0)
    __shared__ float b1s[HID];
    if (threadIdx.x < HID * HID2) {
        int k = threadIdx.x >> 3, j = threadIdx.x & 7;
        Ws2[threadIdx.x] = (j < CLS) ? __ldg(&W2[k * CLS + j]) : 0.0f;
    }
    if (threadIdx.x < HID) b1s[threadIdx.x] = __ldg(&b1[threadIdx.x]);
    __syncthreads();

    int warp = (blockIdx.x * GTPB + threadIdx.x) >> 5;
    if (warp >= N_NODES) return;
    int lane = threadIdx.x & 31;
    int eslot = lane >> 2;          // 0..7
    int q     = lane & 3;           // float4 chunk 0..3

    int beg = __ldg(&g_off[warp]);
    int end = __ldg(&g_off[warp + 1]);

    float4 acc = make_float4(0.f, 0.f, 0.f, 0.f);
    for (int e = beg + eslot; e < end; e += 8) {
        uint2 ent = __ldg(&g_csr[e]);
        float w = __uint_as_float(ent.y);
        float4 v = __ldg((const float4*)(g_h1 + (size_t)ent.x * HID) + q);
        acc.x = fmaf(v.x, w, acc.x);
        acc.y = fmaf(v.y, w, acc.y);
        acc.z = fmaf(v.z, w, acc.z);
        acc.w = fmaf(v.w, w, acc.w);
    }
    #pragma unroll
    for (int m = 4; m <= 16; m <<= 1) {
        acc.x += __shfl_xor_sync(0xffffffffu, acc.x, m);
        acc.y += __shfl_xor_sync(0xffffffffu, acc.y, m);
        acc.z += __shfl_xor_sync(0xffffffffu, acc.z, m);
        acc.w += __shfl_xor_sync(0xffffffffu, acc.w, m);
    }
    // every lane now holds the reduced sum for chunk q = lane & 3
    float dv = __ldg(&g_dinv[warp]);
    float d2 = dv * dv;
    float4 hv = __ldg((const float4*)(g_h1 + (size_t)warp * HID) + q);
    float4 r4;
    r4.x = fmaxf(acc.x + d2 * hv.x + b1s[q * 4 + 0], 0.0f);
    r4.y = fmaxf(acc.y + d2 * hv.y + b1s[q * 4 + 1], 0.0f);
    r4.z = fmaxf(acc.z + d2 * hv.z + b1s[q * 4 + 2], 0.0f);
    r4.w = fmaxf(acc.w + d2 * hv.w + b1s[q * 4 + 3], 0.0f);

    // GEMM2 within warp: lane j (j = lane & 7) computes output column j
    float racc = 0.0f;
    int j = lane & 7;
    #pragma unroll
    for (int qq = 0; qq < 4; qq++) {
        float rx = __shfl_sync(0xffffffffu, r4.x, qq);
        float ry = __shfl_sync(0xffffffffu, r4.y, qq);
        float rz = __shfl_sync(0xffffffffu, r4.z, qq);
        float rw = __shfl_sync(0xffffffffu, r4.w, qq);
        racc = fmaf(rx, Ws2[(qq * 4 + 0) * HID2 + j], racc);
        racc = fmaf(ry, Ws2[(qq * 4 + 1) * HID2 + j], racc);
        racc = fmaf(rz, Ws2[(qq * 4 + 2) * HID2 + j], racc);
        racc = fmaf(rw, Ws2[(qq * 4 + 3) * HID2 + j], racc);
    }
    if (lane < 8) g_h2[(size_t)warp * HID2 + lane] = racc;   // col 7 -> 0 via pad
}

// ---------------- gather layer 2 + finalize -> out ----------------
__global__ void k_gather2(const float* __restrict__ b2, float* __restrict__ out) {
    int warp = (blockIdx.x * GTPB + threadIdx.x) >> 5;
    if (warp >= N_NODES) return;
    int lane = threadIdx.x & 31;
    int eslot = lane >> 1;          // 0..15
    int half  = lane & 1;

    int beg = __ldg(&g_off[warp]);
    int end = __ldg(&g_off[warp + 1]);

    float4 acc = make_float4(0.f, 0.f, 0.f, 0.f);
    for (int e = beg + eslot; e < end; e += 16) {
        uint2 ent = __ldg(&g_csr[e]);
        float w = __uint_as_float(ent.y);
        float4 v = __ldg((const float4*)(g_h2 + (size_t)ent.x * HID2) + half);
        acc.x = fmaf(v.x, w, acc.x);
        acc.y = fmaf(v.y, w, acc.y);
        acc.z = fmaf(v.z, w, acc.z);
        acc.w = fmaf(v.w, w, acc.w);
    }
    #pragma unroll
    for (int m = 2; m <= 16; m <<= 1) {
        acc.x += __shfl_xor_sync(0xffffffffu, acc.x, m);
        acc.y += __shfl_xor_sync(0xffffffffu, acc.y, m);
        acc.z += __shfl_xor_sync(0xffffffffu, acc.z, m);
        acc.w += __shfl_xor_sync(0xffffffffu, acc.w, m);
    }
    if (lane < 2) {
        float dv = __ldg(&g_dinv[warp]);
        float d2 = dv * dv;
        float4 hv = *((const float4*)(g_h2 + (size_t)warp * HID2) + half);
        float o0 = acc.x + d2 * hv.x;
        float o1 = acc.y + d2 * hv.y;
        float o2 = acc.z + d2 * hv.z;
        float o3 = acc.w + d2 * hv.w;
        float* op = out + (size_t)warp * CLS + half * 4;
        if (half == 0) {
            op[0] = o0 + __ldg(&b2[0]);
            op[1] = o1 + __ldg(&b2[1]);
            op[2] = o2 + __ldg(&b2[2]);
            op[3] = o3 + __ldg(&b2[3]);
        } else {
            op[0] = o0 + __ldg(&b2[4]);
            op[1] = o1 + __ldg(&b2[5]);
            op[2] = o2 + __ldg(&b2[6]);
        }
    }
}

// ---------------- launch: fork-join, gemm1 overlapped with edge prep -------
extern "C" void kernel_launch(void* const* d_in, const int* in_sizes, int n_in,
                              void* d_out, int out_size) {
    const float* x  = (const float*)d_in[0];
    const void*  ei = d_in[1];
    const float* W1 = (const float*)d_in[2];
    const float* b1 = (const float*)d_in[3];
    const float* W2 = (const float*)d_in[4];
    const float* b2 = (const float*)d_in[5];
    float* out = (float*)d_out;

    int E = in_sizes[1] / 2;

    static cudaStream_t s2 = nullptr;
    static cudaEvent_t  e0 = nullptr, e1 = nullptr;
    if (s2 == nullptr) {   // first call is the uncaptured correctness run
        cudaStreamCreateWithFlags(&s2, cudaStreamNonBlocking);
        cudaEventCreateWithFlags(&e0, cudaEventDisableTiming);
        cudaEventCreateWithFlags(&e1, cudaEventDisableTiming);
    }

    const int TPB = 256;
    int nbE  = (E + TPB - 1) / TPB;
    int nbG  = (N_NODES * 32 + GTPB - 1) / GTPB;
    int nbG1 = (N_NODES + G1_ROWS - 1) / G1_ROWS;

    // fork: gemm1 on side stream (depends only on x, W1)
    cudaEventRecord(e0, 0);
    cudaStreamWaitEvent(s2, e0, 0);
    k_gemm1<<<nbG1, G1_TPB, 0, s2>>>(x, W1);
    cudaEventRecord(e1, s2);

    // main stream: edge pipeline
    k_detect_zero<<<NB_NODE, TPB>>>((const unsigned int*)ei);
    k_deg  <<<nbE, TPB>>>(ei, E);
    k_scan1<<<NB_NODE, TPB>>>();
    k_scan3<<<NB_NODE, TPB>>>(E);
    k_build<<<nbE, TPB>>>(ei, E);

    // join: gathers need both h1 (gemm1) and csr (build)
    cudaStreamWaitEvent(0, e1, 0);
    k_gather1<<<nbG, GTPB>>>(b1, W2);
    k_gather2<<<nbG, GTPB>>>(b2, out);
}

// round 12
// speedup vs baseline: 1.4950x; 1.0468x over previous
#include <cuda_runtime.h>

#define N_NODES 100000
#define F_IN 512
#define HID 16
#define CLS 7
#define HID2 8
#define E_MAX 3400000
#define NB_NODE 391          // ceil(100000/256)

typedef unsigned long long ull;

// ---------------- device scratch ----------------
__device__ int   g_degi[N_NODES];
__device__ int   g_off [N_NODES + 1];
__device__ int   g_cur [N_NODES];
__device__ int   g_bsum[512];
__device__ float g_dinv[N_NODES];
__device__ __align__(16) float g_h1 [N_NODES * HID];
__device__ __align__(16) float g_h2 [N_NODES * HID2];
__device__ __align__(16) uint2 g_csr[E_MAX];           // {src, bits(weight)}
__device__ int g_is64;

// ---- f32x2 helpers (Blackwell packed fp32 pipe) ----
__device__ __forceinline__ ull fma2(ull a, ull b, ull c) {
    ull d;
    asm("fma.rn.f32x2 %0, %1, %2, %3;" : "=l"(d) : "l"(a), "l"(b), "l"(c));
    return d;
}
__device__ __forceinline__ ull pack2(float a) {
    ull p;
    asm("mov.b64 %0, {%1, %1};" : "=l"(p) : "f"(a));
    return p;
}
__device__ __forceinline__ void unpack2(ull p, float& lo, float& hi) {
    asm("mov.b64 {%0, %1}, %2;" : "=f"(lo), "=f"(hi) : "l"(p));
}

// ---------------- detect dtype + zero degrees (fused) ----------------
__global__ void k_detect_zero(const unsigned int* __restrict__ w) {
    int i = blockIdx.x * blockDim.x + threadIdx.x;
    if (i < N_NODES) g_degi[i] = 0;
    if (i == 0) {
        int all0 = 1;
        #pragma unroll 1
        for (int k = 0; k < 64; k++) {
            long idx = 2L * k * 50001L + 1L;
            if (w[idx] != 0u) all0 = 0;
        }
        g_is64 = all0;
    }
}

// ---------------- degree count (int atomics) ----------------
__global__ void k_deg(const void* __restrict__ ei, int E) {
    int i = blockIdx.x * blockDim.x + threadIdx.x;
    if (i >= E) return;
    int dst;
    if (g_is64) dst = (int)__ldg(&((const long long*)ei)[(size_t)E + i]);
    else        dst = __ldg(&((const int*)ei)[(size_t)E + i]);
    atomicAdd(&g_degi[dst], 1);
}

// ---------------- scan stage 1: per-block exclusive scan ----------------
__global__ void k_scan1() {
    __shared__ int s[256];
    int b = blockIdx.x, t = threadIdx.x;
    int i = b * 256 + t;
    int v = (i < N_NODES) ? g_degi[i] : 0;
    s[t] = v; __syncthreads();
    #pragma unroll
    for (int d = 1; d < 256; d <<= 1) {
        int add = (t >= d) ? s[t - d] : 0;
        __syncthreads();
        s[t] += add;
        __syncthreads();
    }
    if (i < N_NODES) g_off[i] = s[t] - v;   // local exclusive
    if (t == 255) g_bsum[b] = s[255];
}

// ---------------- scan stage 2 (block offsets per-block) + dinv ----------
__global__ void k_scan3(int E) {
    __shared__ int sb[256];
    int t = threadIdx.x, b = blockIdx.x;
    int part = 0;
    for (int j = t; j < b; j += 256) part += g_bsum[j];
    sb[t] = part; __syncthreads();
    #pragma unroll
    for (int d = 128; d > 0; d >>= 1) {
        if (t < d) sb[t] += sb[t + d];
        __syncthreads();
    }
    int boff = sb[0];
    int i = b * 256 + t;
    if (i < N_NODES) {
        int off = g_off[i] + boff;
        g_off[i] = off;
        g_cur[i] = off;
        g_dinv[i] = rsqrtf((float)(g_degi[i] + 1));  // +1 self loop
        if (i == N_NODES - 1) g_off[N_NODES] = E;
    }
}

// ---------------- CSR build: scatter {src, weight} by dst ----------------
__global__ void k_build(const void* __restrict__ ei, int E) {
    int i = blockIdx.x * blockDim.x + threadIdx.x;
    if (i >= E) return;
    int src, dst;
    if (g_is64) {
        const long long* e = (const long long*)ei;
        src = (int)__ldg(&e[i]); dst = (int)__ldg(&e[(size_t)E + i]);
    } else {
        const int* e = (const int*)ei;
        src = __ldg(&e[i]); dst = __ldg(&e[(size_t)E + i]);
    }
    float w = __ldg(&g_dinv[src]) * __ldg(&g_dinv[dst]);
    int pos = atomicAdd(&g_cur[dst], 1);
    g_csr[pos] = make_uint2((unsigned)src, __float_as_uint(w));
}

// ---------------- GEMM1: h1 = x @ W1, 4 rows/thread, f32x2 FMA -----------
#define G1_TPB  128
#define G1_ROWS 512            // rows per block = 4 * G1_TPB
#define KC      16
#define XS2     20             // 16 + pad, multiple of 4
__global__ void __launch_bounds__(G1_TPB)
k_gemm1(const float* __restrict__ x, const float* __restrict__ W1) {
    __shared__ float xs[G1_ROWS * XS2];        // 40 KB
    __shared__ __align__(16) float ws[KC * HID];  // 1 KB

    int t = threadIdx.x;
    int rowbase = blockIdx.x * G1_ROWS;

    ull acc[4][8];                              // 8 f32x2 pairs per row
    #pragma unroll
    for (int r = 0; r < 4; r++)
        #pragma unroll
        for (int j = 0; j < 8; j++) acc[r][j] = 0ULL;

    #pragma unroll 1
    for (int ch = 0; ch < F_IN / KC; ch++) {
        // W chunk: KC*HID = 256 floats = 64 float4
        if (t < 64) {
            const float4* wsrc = (const float4*)(W1 + ch * KC * HID);
            ((float4*)ws)[t] = __ldg(&wsrc[t]);
        }
        // x tile coalesced: 512 rows x 16 cols = 2048 float4, 16 per thread
        #pragma unroll
        for (int i = 0; i < 16; i++) {
            int f   = t + i * G1_TPB;
            int row = f >> 2;                  // 4 float4 per row
            int c4  = f & 3;
            int grow = rowbase + row;
            if (grow >= N_NODES) grow = N_NODES - 1;
            float4 v = __ldg((const float4*)(x + (size_t)grow * F_IN + ch * KC) + c4);
            *(float4*)&xs[row * XS2 + c4 * 4] = v;
        }
        __syncthreads();

        #pragma unroll
        for (int k4 = 0; k4 < KC / 4; k4++) {
            float4 xv0 = *(const float4*)&xs[(t            ) * XS2 + k4 * 4];
            float4 xv1 = *(const float4*)&xs[(t +   G1_TPB ) * XS2 + k4 * 4];
            float4 xv2 = *(const float4*)&xs[(t + 2*G1_TPB ) * XS2 + k4 * 4];
            float4 xv3 = *(const float4*)&xs[(t + 3*G1_TPB ) * XS2 + k4 * 4];
            #pragma unroll
            for (int kk = 0; kk < 4; kk++) {
                const ull* wp = (const ull*)&ws[(k4 * 4 + kk) * HID];
                ull w0 = wp[0], w1 = wp[1], w2 = wp[2], w3 = wp[3];
                ull w4 = wp[4], w5 = wp[5], w6 = wp[6], w7 = wp[7];
                ull p0 = pack2(((const float*)&xv0)[kk]);
                ull p1 = pack2(((const float*)&xv1)[kk]);
                ull p2 = pack2(((const float*)&xv2)[kk]);
                ull p3 = pack2(((const float*)&xv3)[kk]);
                acc[0][0] = fma2(p0, w0, acc[0][0]);
                acc[0][1] = fma2(p0, w1, acc[0][1]);
                acc[0][2] = fma2(p0, w2, acc[0][2]);
                acc[0][3] = fma2(p0, w3, acc[0][3]);
                acc[0][4] = fma2(p0, w4, acc[0][4]);
                acc[0][5] = fma2(p0, w5, acc[0][5]);
                acc[0][6] = fma2(p0, w6, acc[0][6]);
                acc[0][7] = fma2(p0, w7, acc[0][7]);
                acc[1][0] = fma2(p1, w0, acc[1][0]);
                acc[1][1] = fma2(p1, w1, acc[1][1]);
                acc[1][2] = fma2(p1, w2, acc[1][2]);
                acc[1][3] = fma2(p1, w3, acc[1][3]);
                acc[1][4] = fma2(p1, w4, acc[1][4]);
                acc[1][5] = fma2(p1, w5, acc[1][5]);
                acc[1][6] = fma2(p1, w6, acc[1][6]);
                acc[1][7] = fma2(p1, w7, acc[1][7]);
                acc[2][0] = fma2(p2, w0, acc[2][0]);
                acc[2][1] = fma2(p2, w1, acc[2][1]);
                acc[2][2] = fma2(p2, w2, acc[2][2]);
                acc[2][3] = fma2(p2, w3, acc[2][3]);
                acc[2][4] = fma2(p2, w4, acc[2][4]);
                acc[2][5] = fma2(p2, w5, acc[2][5]);
                acc[2][6] = fma2(p2, w6, acc[2][6]);
                acc[2][7] = fma2(p2, w7, acc[2][7]);
                acc[3][0] = fma2(p3, w0, acc[3][0]);
                acc[3][1] = fma2(p3, w1, acc[3][1]);
                acc[3][2] = fma2(p3, w2, acc[3][2]);
                acc[3][3] = fma2(p3, w3, acc[3][3]);
                acc[3][4] = fma2(p3, w4, acc[3][4]);
                acc[3][5] = fma2(p3, w5, acc[3][5]);
                acc[3][6] = fma2(p3, w6, acc[3][6]);
                acc[3][7] = fma2(p3, w7, acc[3][7]);
            }
        }
        __syncthreads();
    }

    #pragma unroll
    for (int r = 0; r < 4; r++) {
        int row = rowbase + t + r * G1_TPB;
        if (row < N_NODES) {
            float4* o = (float4*)(g_h1 + (size_t)row * HID);
            #pragma unroll
            for (int q = 0; q < 4; q++) {
                float a, b, c, d;
                unpack2(acc[r][q * 2],     a, b);
                unpack2(acc[r][q * 2 + 1], c, d);
                o[q] = make_float4(a, b, c, d);
            }
        }
    }
}

// ------- gather layer 1 + selfloop + bias + relu + GEMM2 -> h2 (fused) -----
#define GTPB 256
__global__ void k_gather1(const float* __restrict__ b1, const float* __restrict__ W2) {
    __shared__ float Ws2[HID * HID2];   // W2 padded to 8 cols (col 7 = 0)
    __shared__ float b1s[HID];
    if (threadIdx.x < HID * HID2) {
        int k = threadIdx.x >> 3, j = threadIdx.x & 7;
        Ws2[threadIdx.x] = (j < CLS) ? __ldg(&W2[k * CLS + j]) : 0.0f;
    }
    if (threadIdx.x < HID) b1s[threadIdx.x] = __ldg(&b1[threadIdx.x]);
    __syncthreads();

    int warp = (blockIdx.x * GTPB + threadIdx.x) >> 5;
    if (warp >= N_NODES) return;
    int lane = threadIdx.x & 31;
    int eslot = lane >> 2;          // 0..7
    int q     = lane & 3;           // float4 chunk 0..3

    int beg = __ldg(&g_off[warp]);
    int end = __ldg(&g_off[warp + 1]);

    float4 acc = make_float4(0.f, 0.f, 0.f, 0.f);
    for (int e = beg + eslot; e < end; e += 8) {
        uint2 ent = __ldg(&g_csr[e]);
        float w = __uint_as_float(ent.y);
        float4 v = __ldg((const float4*)(g_h1 + (size_t)ent.x * HID) + q);
        acc.x = fmaf(v.x, w, acc.x);
        acc.y = fmaf(v.y, w, acc.y);
        acc.z = fmaf(v.z, w, acc.z);
        acc.w = fmaf(v.w, w, acc.w);
    }
    #pragma unroll
    for (int m = 4; m <= 16; m <<= 1) {
        acc.x += __shfl_xor_sync(0xffffffffu, acc.x, m);
        acc.y += __shfl_xor_sync(0xffffffffu, acc.y, m);
        acc.z += __shfl_xor_sync(0xffffffffu, acc.z, m);
        acc.w += __shfl_xor_sync(0xffffffffu, acc.w, m);
    }
    float dv = __ldg(&g_dinv[warp]);
    float d2 = dv * dv;
    float4 hv = __ldg((const float4*)(g_h1 + (size_t)warp * HID) + q);
    float4 r4;
    r4.x = fmaxf(acc.x + d2 * hv.x + b1s[q * 4 + 0], 0.0f);
    r4.y = fmaxf(acc.y + d2 * hv.y + b1s[q * 4 + 1], 0.0f);
    r4.z = fmaxf(acc.z + d2 * hv.z + b1s[q * 4 + 2], 0.0f);
    r4.w = fmaxf(acc.w + d2 * hv.w + b1s[q * 4 + 3], 0.0f);

    // GEMM2 within warp: lane j (j = lane & 7) computes output column j
    float racc = 0.0f;
    int j = lane & 7;
    #pragma unroll
    for (int qq = 0; qq < 4; qq++) {
        float rx = __shfl_sync(0xffffffffu, r4.x, qq);
        float ry = __shfl_sync(0xffffffffu, r4.y, qq);
        float rz = __shfl_sync(0xffffffffu, r4.z, qq);
        float rw = __shfl_sync(0xffffffffu, r4.w, qq);
        racc = fmaf(rx, Ws2[(qq * 4 + 0) * HID2 + j], racc);
        racc = fmaf(ry, Ws2[(qq * 4 + 1) * HID2 + j], racc);
        racc = fmaf(rz, Ws2[(qq * 4 + 2) * HID2 + j], racc);
        racc = fmaf(rw, Ws2[(qq * 4 + 3) * HID2 + j], racc);
    }
    if (lane < 8) g_h2[(size_t)warp * HID2 + lane] = racc;   // col 7 -> 0 via pad
}

// ---------------- gather layer 2 + finalize -> out ----------------
__global__ void k_gather2(const float* __restrict__ b2, float* __restrict__ out) {
    int warp = (blockIdx.x * GTPB + threadIdx.x) >> 5;
    if (warp >= N_NODES) return;
    int lane = threadIdx.x & 31;
    int eslot = lane >> 1;          // 0..15
    int half  = lane & 1;

    int beg = __ldg(&g_off[warp]);
    int end = __ldg(&g_off[warp + 1]);

    float4 acc = make_float4(0.f, 0.f, 0.f, 0.f);
    for (int e = beg + eslot; e < end; e += 16) {
        uint2 ent = __ldg(&g_csr[e]);
        float w = __uint_as_float(ent.y);
        float4 v = __ldg((const float4*)(g_h2 + (size_t)ent.x * HID2) + half);
        acc.x = fmaf(v.x, w, acc.x);
        acc.y = fmaf(v.y, w, acc.y);
        acc.z = fmaf(v.z, w, acc.z);
        acc.w = fmaf(v.w, w, acc.w);
    }
    #pragma unroll
    for (int m = 2; m <= 16; m <<= 1) {
        acc.x += __shfl_xor_sync(0xffffffffu, acc.x, m);
        acc.y += __shfl_xor_sync(0xffffffffu, acc.y, m);
        acc.z += __shfl_xor_sync(0xffffffffu, acc.z, m);
        acc.w += __shfl_xor_sync(0xffffffffu, acc.w, m);
    }
    if (lane < 2) {
        float dv = __ldg(&g_dinv[warp]);
        float d2 = dv * dv;
        float4 hv = *((const float4*)(g_h2 + (size_t)warp * HID2) + half);
        float o0 = acc.x + d2 * hv.x;
        float o1 = acc.y + d2 * hv.y;
        float o2 = acc.z + d2 * hv.z;
        float o3 = acc.w + d2 * hv.w;
        float* op = out + (size_t)warp * CLS + half * 4;
        if (half == 0) {
            op[0] = o0 + __ldg(&b2[0]);
            op[1] = o1 + __ldg(&b2[1]);
            op[2] = o2 + __ldg(&b2[2]);
            op[3] = o3 + __ldg(&b2[3]);
        } else {
            op[0] = o0 + __ldg(&b2[4]);
            op[1] = o1 + __ldg(&b2[5]);
            op[2] = o2 + __ldg(&b2[6]);
        }
    }
}

// ---------------- launch: fork-join; gemm1 issued 4th for ncu capture -----
extern "C" void kernel_launch(void* const* d_in, const int* in_sizes, int n_in,
                              void* d_out, int out_size) {
    const float* x  = (const float*)d_in[0];
    const void*  ei = d_in[1];
    const float* W1 = (const float*)d_in[2];
    const float* b1 = (const float*)d_in[3];
    const float* W2 = (const float*)d_in[4];
    const float* b2 = (const float*)d_in[5];
    float* out = (float*)d_out;

    int E = in_sizes[1] / 2;

    static cudaStream_t s2 = nullptr;
    static cudaEvent_t  e0 = nullptr, e1 = nullptr;
    if (s2 == nullptr) {   // first call is the uncaptured correctness run
        cudaStreamCreateWithFlags(&s2, cudaStreamNonBlocking);
        cudaEventCreateWithFlags(&e0, cudaEventDisableTiming);
        cudaEventCreateWithFlags(&e1, cudaEventDisableTiming);
    }

    const int TPB = 256;
    int nbE  = (E + TPB - 1) / TPB;
    int nbG  = (N_NODES * 32 + GTPB - 1) / GTPB;
    int nbG1 = (N_NODES + G1_ROWS - 1) / G1_ROWS;

    cudaEventRecord(e0, 0);
    cudaStreamWaitEvent(s2, e0, 0);

    // main stream: edge pipeline (first 3 issues), then gemm1 issued 4th
    k_detect_zero<<<NB_NODE, TPB>>>((const unsigned int*)ei);
    k_deg  <<<nbE, TPB>>>(ei, E);
    k_scan1<<<NB_NODE, TPB>>>();

    k_gemm1<<<nbG1, G1_TPB, 0, s2>>>(x, W1);   // 4th issued launch -> ncu target
    cudaEventRecord(e1, s2);

    k_scan3<<<NB_NODE, TPB>>>(E);
    k_build<<<nbE, TPB>>>(ei, E);

    // join: gathers need both h1 (gemm1) and csr (build)
    cudaStreamWaitEvent(0, e1, 0);
    k_gather1<<<nbG, GTPB>>>(b1, W2);
    k_gather2<<<nbG, GTPB>>>(b2, out);
}